// round 1
// baseline (speedup 1.0000x reference)
#include <cuda_runtime.h>
#include <math.h>

#define NN 8192
#define KK 32
#define NT 64                     // 8192/128 tiles per dim
#define NTILES (NT*(NT+1)/2)      // 2080 upper-triangular tiles

// ---- scratch (no allocations allowed) ----
__device__ float  d_Xs  [KK*NN];        // softmax(X) (K,N)
__device__ float  d_Cst [KK*NN];        // softmax(C) transposed -> (K,N)
__device__ float  d_Epart[64*KK*KK];    // partial E per i-chunk
__device__ float  d_Ya  [KK*NN];        // 2a * M @ X
__device__ float  d_bv  [NN];           // beta - a*q
__device__ double d_partSP[NTILES];
__device__ double d_partTA[NTILES];

// ---------- column softmax of X over K=32 rows ----------
__global__ void k_softmax_x(const float* __restrict__ X) {
    int i = blockIdx.x * blockDim.x + threadIdx.x;
    float v[KK];
    float m = -1e30f;
#pragma unroll
    for (int p = 0; p < KK; p++) { v[p] = X[p*NN + i]; m = fmaxf(m, v[p]); }
    float s = 0.f;
#pragma unroll
    for (int p = 0; p < KK; p++) { v[p] = __expf(v[p] - m); s += v[p]; }
    float inv = 1.f / s;
#pragma unroll
    for (int p = 0; p < KK; p++) d_Xs[p*NN + i] = v[p] * inv;
}

// ---------- column softmax of C over N=8192 rows, store transposed ----------
__global__ void k_softmax_c(const float* __restrict__ C) {
    int k = blockIdx.x, t = threadIdx.x;
    __shared__ float red[256];
    float m = -1e30f;
    for (int i = t; i < NN; i += 256) m = fmaxf(m, C[i*KK + k]);
    red[t] = m; __syncthreads();
    for (int s = 128; s > 0; s >>= 1) { if (t < s) red[t] = fmaxf(red[t], red[t+s]); __syncthreads(); }
    m = red[0]; __syncthreads();
    float sum = 0.f;
    for (int i = t; i < NN; i += 256) sum += __expf(C[i*KK + k] - m);
    red[t] = sum; __syncthreads();
    for (int s = 128; s > 0; s >>= 1) { if (t < s) red[t] += red[t+s]; __syncthreads(); }
    float inv = 1.f / red[0];
    for (int i = t; i < NN; i += 256) d_Cst[k*NN + i] = __expf(C[i*KK + k] - m) * inv;
}

// ---------- partial E = Xs @ Cs over a 128-wide i-chunk ----------
__global__ void k_epart() {
    __shared__ float xs[KK][132];
    __shared__ float cs[KK][132];
    int blk = blockIdx.x, tid = threadIdx.x;
    int base = blk * 128;
#pragma unroll
    for (int c = 0; c < 4; c++) {
        int e = c*1024 + tid*4;
        int p = e >> 7, ii = e & 127;
        *(float4*)&xs[p][ii] = *(const float4*)&d_Xs [p*NN + base + ii];
        *(float4*)&cs[p][ii] = *(const float4*)&d_Cst[p*NN + base + ii];
    }
    __syncthreads();
    int p = tid >> 3, k0 = (tid & 7) * 4;
    float a0 = 0.f, a1 = 0.f, a2 = 0.f, a3 = 0.f;
#pragma unroll 4
    for (int ii = 0; ii < 128; ii++) {
        float xv = xs[p][ii];
        a0 += xv * cs[k0+0][ii];
        a1 += xv * cs[k0+1][ii];
        a2 += xv * cs[k0+2][ii];
        a3 += xv * cs[k0+3][ii];
    }
    float* out = &d_Epart[blk*1024 + p*32 + k0];
    out[0] = a0; out[1] = a1; out[2] = a2; out[3] = a3;
}

// ---------- reduce E, build M = E^T E, compute Ya = 2a*M*X, b = beta - a*q ----------
__global__ void k_ya(const float* __restrict__ X, const float* __restrict__ beta,
                     const float* __restrict__ a_p) {
    __shared__ float Es[KK*KK];
    __shared__ float Ms[KK][KK+1];
    int tid = threadIdx.x;
#pragma unroll
    for (int c = 0; c < 4; c++) {
        int e = tid*4 + c;
        float s = 0.f;
        for (int b = 0; b < 64; b++) s += d_Epart[b*1024 + e];
        Es[e] = s;
    }
    __syncthreads();
#pragma unroll
    for (int c = 0; c < 4; c++) {
        int e = tid*4 + c;
        int p = e >> 5, q = e & 31;
        float s = 0.f;
#pragma unroll
        for (int r = 0; r < KK; r++) s += Es[r*KK + p] * Es[r*KK + q];
        Ms[p][q] = s;
    }
    __syncthreads();
    int i = blockIdx.x * 256 + tid;
    float a = a_p[0];
    float xv[KK];
#pragma unroll
    for (int q = 0; q < KK; q++) xv[q] = X[q*NN + i];
    float qf = 0.f;
    float twoa = 2.f * a;
#pragma unroll
    for (int p = 0; p < KK; p++) {
        float tp = 0.f;
#pragma unroll
        for (int q = 0; q < KK; q++) tp += Ms[p][q] * xv[q];
        d_Ya[p*NN + i] = twoa * tp;
        qf += xv[p] * tp;
    }
    d_bv[i] = beta[i] - a * qf;
}

__device__ __forceinline__ float softplusf(float x) {
    return fmaxf(x, 0.f) + log1pf(__expf(-fabsf(x)));
}

// ---------- main pair kernel: one 128x128 tile per block, upper triangle ----------
__global__ void __launch_bounds__(256, 2)
k_pairs(const float* __restrict__ X, const float* __restrict__ A) {
    __shared__ float Xt[KK][128];
    __shared__ float Yt[KK][128];
    __shared__ float bI[128];
    __shared__ float bJ[128];
    __shared__ float wSP[8], wTA[8];

    // linear tile id -> (I, J) with I <= J
    int t = blockIdx.x;
    int I = 0;
    { int rem = t, rl = NT; while (rem >= rl) { rem -= rl; rl--; I++; } t = rem; }
    int J = I + t;
    int iBase = I * 128, jBase = J * 128;
    int tid = threadIdx.x;

#pragma unroll
    for (int c = 0; c < 4; c++) {
        int e = c*1024 + tid*4;
        int p = e >> 7, ii = e & 127;
        *(float4*)&Xt[p][ii] = *(const float4*)&X   [p*NN + iBase + ii];
        *(float4*)&Yt[p][ii] = *(const float4*)&d_Ya[p*NN + jBase + ii];
    }
    if (tid < 128) bI[tid] = d_bv[iBase + tid];
    else           bJ[tid - 128] = d_bv[jBase + tid - 128];
    __syncthreads();

    int tx = tid & 15, ty = tid >> 4;
    // thread covers rows iBase+ty*8+[0..8), cols jBase + {tx*4+[0..4), 64+tx*4+[0..4)}
    float acc[8][8];
#pragma unroll
    for (int r = 0; r < 8; r++)
#pragma unroll
        for (int c = 0; c < 8; c++) acc[r][c] = 0.f;

#pragma unroll
    for (int k = 0; k < KK; k++) {
        float4 xa = *(float4*)&Xt[k][ty*8];
        float4 xb = *(float4*)&Xt[k][ty*8 + 4];
        float4 ya = *(float4*)&Yt[k][tx*4];
        float4 yb = *(float4*)&Yt[k][64 + tx*4];
        float xf[8] = {xa.x, xa.y, xa.z, xa.w, xb.x, xb.y, xb.z, xb.w};
        float yf[8] = {ya.x, ya.y, ya.z, ya.w, yb.x, yb.y, yb.z, yb.w};
#pragma unroll
        for (int r = 0; r < 8; r++)
#pragma unroll
            for (int c = 0; c < 8; c++) acc[r][c] += xf[r] * yf[c];
    }

    float bIr[8], bJc[8];
#pragma unroll
    for (int r = 0; r < 8; r++) bIr[r] = bI[ty*8 + r];
#pragma unroll
    for (int c = 0; c < 4; c++) { bJc[c] = bJ[tx*4 + c]; bJc[c+4] = bJ[64 + tx*4 + c]; }
#pragma unroll
    for (int r = 0; r < 8; r++)
#pragma unroll
        for (int c = 0; c < 8; c++) acc[r][c] += bIr[r] + bJc[c];   // acc now holds theta

    float sSP = 0.f, sTA = 0.f;

    if (I != J) {
#pragma unroll
        for (int r = 0; r < 8; r++) {
            int gi = iBase + ty*8 + r;
            float4 a0 = __ldcs((const float4*)&A[gi*NN + jBase + tx*4]);
            float4 a1 = __ldcs((const float4*)&A[gi*NN + jBase + 64 + tx*4]);
            float av[8] = {a0.x, a0.y, a0.z, a0.w, a1.x, a1.y, a1.z, a1.w};
#pragma unroll
            for (int c = 0; c < 8; c++) {
                float th = acc[r][c];
                sSP += 2.f * softplusf(th);
                sTA += th * av[c];
            }
        }
#pragma unroll
        for (int c = 0; c < 8; c++) {
            int gj = jBase + ((c < 4) ? (tx*4 + c) : (64 + tx*4 + (c - 4)));
            float4 b0 = __ldcs((const float4*)&A[gj*NN + iBase + ty*8]);
            float4 b1 = __ldcs((const float4*)&A[gj*NN + iBase + ty*8 + 4]);
            float atv[8] = {b0.x, b0.y, b0.z, b0.w, b1.x, b1.y, b1.z, b1.w};
#pragma unroll
            for (int r = 0; r < 8; r++) sTA += acc[r][c] * atv[r];
        }
    } else {
        // diagonal tile: only i<j contributes sp (x2); i==j contributes theta*A_ii
#pragma unroll
        for (int r = 0; r < 8; r++) {
            int gi = iBase + ty*8 + r;
            float4 a0 = __ldcs((const float4*)&A[gi*NN + jBase + tx*4]);
            float4 a1 = __ldcs((const float4*)&A[gi*NN + jBase + 64 + tx*4]);
            float av[8] = {a0.x, a0.y, a0.z, a0.w, a1.x, a1.y, a1.z, a1.w};
#pragma unroll
            for (int c = 0; c < 8; c++) {
                int gj = jBase + ((c < 4) ? (tx*4 + c) : (64 + tx*4 + (c - 4)));
                float th = acc[r][c];
                if (gi < gj) {
                    sSP += 2.f * softplusf(th);
                    sTA += th * av[c];
                } else if (gi == gj) {
                    sTA += th * av[c];
                }
            }
        }
#pragma unroll
        for (int c = 0; c < 8; c++) {
            int gj = jBase + ((c < 4) ? (tx*4 + c) : (64 + tx*4 + (c - 4)));
            float4 b0 = __ldcs((const float4*)&A[gj*NN + iBase + ty*8]);
            float4 b1 = __ldcs((const float4*)&A[gj*NN + iBase + ty*8 + 4]);
            float atv[8] = {b0.x, b0.y, b0.z, b0.w, b1.x, b1.y, b1.z, b1.w};
#pragma unroll
            for (int r = 0; r < 8; r++) {
                int gi = iBase + ty*8 + r;
                if (gi < gj) sTA += acc[r][c] * atv[r];
            }
        }
    }

    // deterministic block reduction (no atomics)
#pragma unroll
    for (int o = 16; o > 0; o >>= 1) {
        sSP += __shfl_xor_sync(0xffffffffu, sSP, o);
        sTA += __shfl_xor_sync(0xffffffffu, sTA, o);
    }
    int wid = tid >> 5, lane = tid & 31;
    if (lane == 0) { wSP[wid] = sSP; wTA[wid] = sTA; }
    __syncthreads();
    if (tid == 0) {
        float s1 = 0.f, s2 = 0.f;
#pragma unroll
        for (int w = 0; w < 8; w++) { s1 += wSP[w]; s2 += wTA[w]; }
        d_partSP[blockIdx.x] = (double)s1;
        d_partTA[blockIdx.x] = (double)s2;
    }
}

// ---------- deterministic final reduction ----------
__global__ void k_final(float* __restrict__ out) {
    __shared__ double rSP[256], rTA[256];
    int t = threadIdx.x;
    double s1 = 0.0, s2 = 0.0;
    for (int i = t; i < NTILES; i += 256) { s1 += d_partSP[i]; s2 += d_partTA[i]; }
    rSP[t] = s1; rTA[t] = s2; __syncthreads();
    for (int s = 128; s > 0; s >>= 1) {
        if (t < s) { rSP[t] += rSP[t+s]; rTA[t] += rTA[t+s]; }
        __syncthreads();
    }
    if (t == 0) out[0] = (float)(0.5 * rTA[0] - 0.5 * rSP[0]);
}

extern "C" void kernel_launch(void* const* d_in, const int* in_sizes, int n_in,
                              void* d_out, int out_size) {
    const float* A    = (const float*)d_in[0];
    const float* beta = (const float*)d_in[1];
    const float* a    = (const float*)d_in[2];
    const float* X    = (const float*)d_in[3];
    const float* C    = (const float*)d_in[4];
    float* out = (float*)d_out;

    k_softmax_x<<<NN/256, 256>>>(X);
    k_softmax_c<<<KK, 256>>>(C);
    k_epart<<<64, 256>>>();
    k_ya<<<NN/256, 256>>>(X, beta, a);
    k_pairs<<<NTILES, 256>>>(X, A);
    k_final<<<1, 256>>>(out);
}

// round 2
// speedup vs baseline: 1.5856x; 1.5856x over previous
#include <cuda_runtime.h>
#include <math.h>

#define NN 8192
#define KK 32
#define NT 64                     // 8192/128 tiles per dim
#define NTILES (NT*(NT+1)/2)      // 2080 upper-triangular tiles

typedef unsigned long long u64;

#define FMA2(d,a,b,c) asm("fma.rn.f32x2 %0, %1, %2, %3;" : "=l"(d) : "l"(a), "l"(b), "l"(c))
#define PK2(d,lo,hi)  asm("mov.b64 %0, {%1, %2};" : "=l"(d) : "f"(lo), "f"(hi))
#define UPK2(lo,hi,s) asm("mov.b64 {%0, %1}, %2;" : "=f"(lo), "=f"(hi) : "l"(s))

// ---- scratch (no allocations allowed) ----
__device__ float  d_Xs  [KK*NN];        // softmax(X) (K,N)
__device__ float  d_Cst [KK*NN];        // softmax(C) transposed -> (K,N)
__device__ float  d_Epart[64*KK*KK];    // partial E per i-chunk
__device__ float  d_M   [KK*KK];        // M = E^T E
__device__ float  d_Ya  [KK*NN];        // 2a * M @ X
__device__ float  d_bv  [NN];           // beta - a*q
__device__ float  d_cpm [64*KK];        // per-block column max partials of C
__device__ float  d_cps [64*KK];        // per-block column sum partials of C
__device__ float  d_cm  [KK];
__device__ float  d_cinv[KK];
__device__ double d_partSP[NTILES];
__device__ double d_partTA[NTILES];

// ---------- column softmax of X over K=32 rows ----------
__global__ void k_softmax_x(const float* __restrict__ X) {
    int i = blockIdx.x * 128 + threadIdx.x;
    float v[KK];
    float m = -1e30f;
#pragma unroll
    for (int p = 0; p < KK; p++) { v[p] = X[p*NN + i]; m = fmaxf(m, v[p]); }
    float s = 0.f;
#pragma unroll
    for (int p = 0; p < KK; p++) { v[p] = __expf(v[p] - m); s += v[p]; }
    float inv = 1.f / s;
#pragma unroll
    for (int p = 0; p < KK; p++) d_Xs[p*NN + i] = v[p] * inv;
}

// ---------- C column-softmax phase 1: coalesced online (max,sum) partials ----------
__global__ void k_cstat(const float* __restrict__ C) {
    int blk = blockIdx.x, tid = threadIdx.x;
    int c = tid & 31, rs = tid >> 5;
    int rowBase = blk * 128;
    float m = -1e30f, s = 0.f;
#pragma unroll
    for (int it = 0; it < 16; it++) {
        float v = C[(rowBase + rs + it*8)*KK + c];
        float nm = fmaxf(m, v);
        s = s * __expf(m - nm) + __expf(v - nm);
        m = nm;
    }
    __shared__ float sm[8][32], ss[8][32];
    sm[rs][c] = m; ss[rs][c] = s;
    __syncthreads();
    if (tid < 32) {
        float M0 = sm[0][tid], S0 = ss[0][tid];
#pragma unroll
        for (int r = 1; r < 8; r++) {
            float nm = fmaxf(M0, sm[r][tid]);
            S0 = S0 * __expf(M0 - nm) + ss[r][tid] * __expf(sm[r][tid] - nm);
            M0 = nm;
        }
        d_cpm[blk*32 + tid] = M0;
        d_cps[blk*32 + tid] = S0;
    }
}

// ---------- phase 2: combine 64 partials per column ----------
__global__ void k_cfin() {
    int c = threadIdx.x;
    float M = -1e30f, S = 0.f;
    for (int b = 0; b < 64; b++) {
        float m = d_cpm[b*32 + c], s = d_cps[b*32 + c];
        float nm = fmaxf(M, m);
        S = S * __expf(M - nm) + s * __expf(m - nm);
        M = nm;
    }
    d_cm[c] = M;
    d_cinv[c] = 1.f / S;
}

// ---------- phase 3: write softmax(C) transposed, coalesced both sides ----------
__global__ void k_cst(const float* __restrict__ C) {
    __shared__ float tile[32][132];
    int blk = blockIdx.x, tid = threadIdx.x;
    int c = tid & 31, rs = tid >> 5;
    int rowBase = blk * 128;
    float m = d_cm[c], inv = d_cinv[c];
#pragma unroll
    for (int it = 0; it < 16; it++) {
        int row = rs + it*8;
        float v = C[(rowBase + row)*KK + c];
        tile[c][row] = __expf(v - m) * inv;
    }
    __syncthreads();
    int cc = tid >> 3, j0 = (tid & 7) * 16;
#pragma unroll
    for (int j = 0; j < 16; j += 4)
        *(float4*)&d_Cst[cc*NN + rowBase + j0 + j] = *(float4*)&tile[cc][j0 + j];
}

// ---------- partial E = Xs @ Cs over a 128-wide i-chunk ----------
__global__ void k_epart() {
    __shared__ float xs[KK][132];
    __shared__ float cs[KK][132];
    int blk = blockIdx.x, tid = threadIdx.x;
    int base = blk * 128;
#pragma unroll
    for (int c = 0; c < 4; c++) {
        int e = c*1024 + tid*4;
        int p = e >> 7, ii = e & 127;
        *(float4*)&xs[p][ii] = *(const float4*)&d_Xs [p*NN + base + ii];
        *(float4*)&cs[p][ii] = *(const float4*)&d_Cst[p*NN + base + ii];
    }
    __syncthreads();
    int p = tid >> 3, k0 = (tid & 7) * 4;
    float a0 = 0.f, a1 = 0.f, a2 = 0.f, a3 = 0.f;
#pragma unroll 4
    for (int ii = 0; ii < 128; ii++) {
        float xv = xs[p][ii];
        a0 += xv * cs[k0+0][ii];
        a1 += xv * cs[k0+1][ii];
        a2 += xv * cs[k0+2][ii];
        a3 += xv * cs[k0+3][ii];
    }
    float* out = &d_Epart[blk*1024 + p*32 + k0];
    out[0] = a0; out[1] = a1; out[2] = a2; out[3] = a3;
}

// ---------- reduce Epart -> E, compute M = E^T E (once) ----------
__global__ void k_M() {
    __shared__ float Es[KK*KK];
    int tid = threadIdx.x;
#pragma unroll
    for (int c = 0; c < 4; c++) {
        int e = tid*4 + c;
        float s = 0.f;
#pragma unroll 8
        for (int b = 0; b < 64; b++) s += d_Epart[b*1024 + e];
        Es[e] = s;
    }
    __syncthreads();
#pragma unroll
    for (int c = 0; c < 4; c++) {
        int e = tid*4 + c;
        int p = e >> 5, q = e & 31;
        float s = 0.f;
#pragma unroll
        for (int r = 0; r < KK; r++) s += Es[r*KK + p] * Es[r*KK + q];
        d_M[e] = s;
    }
}

// ---------- Ya = 2a*M*X, b = beta - a*q ----------
__global__ void k_ya(const float* __restrict__ X, const float* __restrict__ beta,
                     const float* __restrict__ a_p) {
    __shared__ float Ms[KK][KK+1];
    int tid = threadIdx.x;
    for (int idx = tid; idx < KK*KK; idx += 128)
        Ms[idx >> 5][idx & 31] = d_M[idx];
    __syncthreads();
    int i = blockIdx.x * 128 + tid;
    float a = a_p[0];
    float xv[KK];
#pragma unroll
    for (int q = 0; q < KK; q++) xv[q] = X[q*NN + i];
    float qf = 0.f;
    float twoa = 2.f * a;
#pragma unroll
    for (int p = 0; p < KK; p++) {
        float tp = 0.f;
#pragma unroll
        for (int q = 0; q < KK; q++) tp += Ms[p][q] * xv[q];
        d_Ya[p*NN + i] = twoa * tp;
        qf += xv[p] * tp;
    }
    d_bv[i] = beta[i] - a * qf;
}

__device__ __forceinline__ float softplusf(float x) {
    // max(x,0) + log(1 + exp(-|x|)); fast-math variant, 2 MUFU ops
    return fmaxf(x, 0.f) + __logf(1.f + __expf(-fabsf(x)));
}

// ---------- main pair kernel: one 128x128 tile per block, upper triangle ----------
__global__ void __launch_bounds__(256, 2)
k_pairs(const float* __restrict__ X, const float* __restrict__ A) {
    __shared__ float Xt[KK][128];
    __shared__ float Yt[KK][128];
    __shared__ float bI[128];
    __shared__ float bJ[128];
    __shared__ float wSP[8], wTA[8];

    // linear tile id -> (I, J) with I <= J
    int t = blockIdx.x;
    int I = 0;
    { int rem = t, rl = NT; while (rem >= rl) { rem -= rl; rl--; I++; } t = rem; }
    int J = I + t;
    int iBase = I * 128, jBase = J * 128;
    int tid = threadIdx.x;

#pragma unroll
    for (int c = 0; c < 4; c++) {
        int e = c*1024 + tid*4;
        int p = e >> 7, ii = e & 127;
        *(float4*)&Xt[p][ii] = *(const float4*)&X   [p*NN + iBase + ii];
        *(float4*)&Yt[p][ii] = *(const float4*)&d_Ya[p*NN + jBase + ii];
    }
    if (tid < 128) bI[tid] = d_bv[iBase + tid];
    else           bJ[tid - 128] = d_bv[jBase + tid - 128];
    __syncthreads();

    int tx = tid & 15, ty = tid >> 4;
    // thread covers rows iBase+ty*8+[0..8), cols jBase + {tx*4+[0..4), 64+tx*4+[0..4)}
    float bIr[8], bJc[8];
#pragma unroll
    for (int r = 0; r < 8; r++) bIr[r] = bI[ty*8 + r];
#pragma unroll
    for (int c = 0; c < 4; c++) { bJc[c] = bJ[tx*4 + c]; bJc[c+4] = bJ[64 + tx*4 + c]; }

    // packed accumulators, initialized with the bias so theta falls out directly
    u64 acc2[8][4];
#pragma unroll
    for (int r = 0; r < 8; r++)
#pragma unroll
        for (int cp = 0; cp < 4; cp++) {
            float lo = bIr[r] + bJc[2*cp];
            float hi = bIr[r] + bJc[2*cp + 1];
            PK2(acc2[r][cp], lo, hi);
        }

#pragma unroll
    for (int k = 0; k < KK; k++) {
        float4 xa = *(float4*)&Xt[k][ty*8];
        float4 xb = *(float4*)&Xt[k][ty*8 + 4];
        const u64* yp0 = (const u64*)&Yt[k][tx*4];
        const u64* yp1 = (const u64*)&Yt[k][64 + tx*4];
        u64 y2[4] = {yp0[0], yp0[1], yp1[0], yp1[1]};
        float xf[8] = {xa.x, xa.y, xa.z, xa.w, xb.x, xb.y, xb.z, xb.w};
#pragma unroll
        for (int r = 0; r < 8; r++) {
            u64 xx;
            PK2(xx, xf[r], xf[r]);
#pragma unroll
            for (int cp = 0; cp < 4; cp++)
                FMA2(acc2[r][cp], xx, y2[cp], acc2[r][cp]);
        }
    }
    // acc2 now holds theta (packed pairs of columns)

    float sSP = 0.f, sTA = 0.f;
    u64 sTA2; PK2(sTA2, 0.f, 0.f);

    if (I != J) {
#pragma unroll
        for (int r = 0; r < 8; r++) {
            int gi = iBase + ty*8 + r;
            float4 a0 = __ldcs((const float4*)&A[gi*NN + jBase + tx*4]);
            float4 a1 = __ldcs((const float4*)&A[gi*NN + jBase + 64 + tx*4]);
            u64 a2[4];
            PK2(a2[0], a0.x, a0.y); PK2(a2[1], a0.z, a0.w);
            PK2(a2[2], a1.x, a1.y); PK2(a2[3], a1.z, a1.w);
#pragma unroll
            for (int cp = 0; cp < 4; cp++) {
                float t0, t1;
                UPK2(t0, t1, acc2[r][cp]);
                sSP += softplusf(t0) + softplusf(t1);
                FMA2(sTA2, acc2[r][cp], a2[cp], sTA2);
            }
        }
        // transposed A block
#pragma unroll
        for (int c = 0; c < 8; c++) {
            int gj = jBase + ((c < 4) ? (tx*4 + c) : (64 + tx*4 + (c - 4)));
            float4 b0 = __ldcs((const float4*)&A[gj*NN + iBase + ty*8]);
            float4 b1 = __ldcs((const float4*)&A[gj*NN + iBase + ty*8 + 4]);
            float atv[8] = {b0.x, b0.y, b0.z, b0.w, b1.x, b1.y, b1.z, b1.w};
            int cp = c >> 1;
#pragma unroll
            for (int r = 0; r < 8; r++) {
                float t0, t1;
                UPK2(t0, t1, acc2[r][cp]);
                float th = (c & 1) ? t1 : t0;
                sTA += th * atv[r];
            }
        }
        sSP *= 2.f;
    } else {
        // diagonal tile: only i<j contributes sp (x2); i==j contributes theta*A_ii
#pragma unroll
        for (int r = 0; r < 8; r++) {
            int gi = iBase + ty*8 + r;
            float4 a0 = __ldcs((const float4*)&A[gi*NN + jBase + tx*4]);
            float4 a1 = __ldcs((const float4*)&A[gi*NN + jBase + 64 + tx*4]);
            float av[8] = {a0.x, a0.y, a0.z, a0.w, a1.x, a1.y, a1.z, a1.w};
#pragma unroll
            for (int c = 0; c < 8; c++) {
                int gj = jBase + ((c < 4) ? (tx*4 + c) : (64 + tx*4 + (c - 4)));
                float t0, t1;
                UPK2(t0, t1, acc2[r][c >> 1]);
                float th = (c & 1) ? t1 : t0;
                if (gi < gj) {
                    sSP += 2.f * softplusf(th);
                    sTA += th * av[c];
                } else if (gi == gj) {
                    sTA += th * av[c];
                }
            }
        }
#pragma unroll
        for (int c = 0; c < 8; c++) {
            int gj = jBase + ((c < 4) ? (tx*4 + c) : (64 + tx*4 + (c - 4)));
            float4 b0 = __ldcs((const float4*)&A[gj*NN + iBase + ty*8]);
            float4 b1 = __ldcs((const float4*)&A[gj*NN + iBase + ty*8 + 4]);
            float atv[8] = {b0.x, b0.y, b0.z, b0.w, b1.x, b1.y, b1.z, b1.w};
#pragma unroll
            for (int r = 0; r < 8; r++) {
                int gi = iBase + ty*8 + r;
                float t0, t1;
                UPK2(t0, t1, acc2[r][c >> 1]);
                float th = (c & 1) ? t1 : t0;
                if (gi < gj) sTA += th * atv[r];
            }
        }
    }

    {
        float t0, t1;
        UPK2(t0, t1, sTA2);
        sTA += t0 + t1;
    }

    // deterministic block reduction (no atomics)
#pragma unroll
    for (int o = 16; o > 0; o >>= 1) {
        sSP += __shfl_xor_sync(0xffffffffu, sSP, o);
        sTA += __shfl_xor_sync(0xffffffffu, sTA, o);
    }
    int wid = tid >> 5, lane = tid & 31;
    if (lane == 0) { wSP[wid] = sSP; wTA[wid] = sTA; }
    __syncthreads();
    if (tid == 0) {
        float s1 = 0.f, s2 = 0.f;
#pragma unroll
        for (int w = 0; w < 8; w++) { s1 += wSP[w]; s2 += wTA[w]; }
        d_partSP[blockIdx.x] = (double)s1;
        d_partTA[blockIdx.x] = (double)s2;
    }
}

// ---------- deterministic final reduction ----------
__global__ void k_final(float* __restrict__ out) {
    __shared__ double rSP[256], rTA[256];
    int t = threadIdx.x;
    double s1 = 0.0, s2 = 0.0;
    for (int i = t; i < NTILES; i += 256) { s1 += d_partSP[i]; s2 += d_partTA[i]; }
    rSP[t] = s1; rTA[t] = s2; __syncthreads();
    for (int s = 128; s > 0; s >>= 1) {
        if (t < s) { rSP[t] += rSP[t+s]; rTA[t] += rTA[t+s]; }
        __syncthreads();
    }
    if (t == 0) out[0] = (float)(0.5 * rTA[0] - 0.5 * rSP[0]);
}

extern "C" void kernel_launch(void* const* d_in, const int* in_sizes, int n_in,
                              void* d_out, int out_size) {
    const float* A    = (const float*)d_in[0];
    const float* beta = (const float*)d_in[1];
    const float* a    = (const float*)d_in[2];
    const float* X    = (const float*)d_in[3];
    const float* C    = (const float*)d_in[4];
    float* out = (float*)d_out;

    k_softmax_x<<<NN/128, 128>>>(X);
    k_cstat<<<64, 256>>>(C);
    k_cfin<<<1, 32>>>();
    k_cst<<<64, 256>>>(C);
    k_epart<<<64, 256>>>();
    k_M<<<1, 256>>>();
    k_ya<<<NN/128, 128>>>(X, beta, a);
    k_pairs<<<NTILES, 256>>>(X, A);
    k_final<<<1, 256>>>(out);
}